// round 9
// baseline (speedup 1.0000x reference)
#include <cuda_runtime.h>
#include <cstdint>

#define P_GAIN     2.0f
#define P_BASELINE 100.0f
static constexpr int B = 32;
static constexpr int E = 64;
static constexpr int H = 128;
static constexpr int W = 128;
static constexpr int R = 13;
static constexpr int D = 32;
static constexpr int HALF = R / 2;
static constexpr int PIX = H * W;               // 16384
static constexpr int NPX = R * R;               // 169 patch pixels
static constexpr int PPAD = 176;                // padded patch stride
static constexpr int SLPAD = 68;                // slice row pad (16B aligned)
static constexpr int BAND = 8;                  // rows per band
static constexpr int NBAND = H / BAND;          // 16
static constexpr int BAND_F4 = BAND * W / 4;    // 256 float4 per band
static constexpr int BAND_BYTES = BAND * W * 4; // 4096
static constexpr int NSPLIT = 8;                // emitter splits per z-slice
static constexpr int ESPLIT = 4;                // emitter splits in render
static constexpr int EPB = E / ESPLIT;          // 16 emitters per render block

// Scratch (static device global — no allocation)
__device__ float g_patch[B * E * PPAD];         // 1.44 MB pre-scaled patches

// ---------------------------------------------------------------------------
// Kernel 1: z-grouped patch precompute (flat task loop). Fires the PDL
// trigger at entry so the render kernel can launch and run its independent
// prefix (bg staging, classification, miss-emitter bulk copies) concurrently.
// ---------------------------------------------------------------------------
__global__ __launch_bounds__(256) void patch_kernel(const float* __restrict__ xyz,
                                                    const float* __restrict__ nph,
                                                    const float* __restrict__ coeff)
{
    cudaTriggerProgrammaticLaunchCompletion();

    const int z     = blockIdx.x;    // 0..D-1
    const int split = blockIdx.y;    // 0..NSPLIT-1
    const int t     = threadIdx.x;

    __shared__ float s_sl[NPX * SLPAD];  // 45.97 KB padded slice
    __shared__ int   s_list[256];
    __shared__ int   s_n;

    if (t == 0) s_n = 0;

    // ---- stage slice (coalesced float4 in, aligned STS.128 out) ----
    const float4* __restrict__ c4 =
        reinterpret_cast<const float4*>(coeff + (size_t)z * NPX * 64);
    #pragma unroll 4
    for (int i4 = t; i4 < NPX * 16; i4 += 256) {   // 2704 float4
        const float4 f = c4[i4];
        const int pix = i4 >> 4;
        const int k4  = i4 & 15;
        reinterpret_cast<float4*>(&s_sl[pix * SLPAD])[k4] = f;
    }

    // ---- build emitter list for this (z, split) ----
    for (int e = t; e < B * E; e += 256) {
        if ((e & (NSPLIT - 1)) != split) continue;
        const float zv = xyz[e * 3 + 2];
        float zc = fminf(fmaxf(zv, 0.0f), (float)(D - 1) - 1e-6f);
        if ((int)floorf(zc) == z) s_list[atomicAdd(&s_n, 1)] = e;
    }
    __syncthreads();

    // ---- flat task loop: task = (listed emitter, patch pixel) ----
    const int n = s_n;
    const int work = n * NPX;
    for (int i = t; i < work; i += 256) {
        const int h  = i / NPX;
        const int p  = i - h * NPX;
        const int ge = s_list[h];

        const float x  = xyz[ge * 3 + 0];
        const float y  = xyz[ge * 3 + 1];
        const float zv = xyz[ge * 3 + 2];
        const float dx = x - floorf(x);
        const float dy = y - floorf(y);
        float zc = fminf(fmaxf(zv, 0.0f), (float)(D - 1) - 1e-6f);
        const float dz = zc - floorf(zc);
        const float amp = nph[ge] * P_GAIN;

        float pxv[4], pyv[4], pzv[4];
        pxv[0] = 1.0f; pxv[1] = dx; pxv[2] = dx * dx; pxv[3] = pxv[2] * dx;
        pyv[0] = 1.0f; pyv[1] = dy; pyv[2] = dy * dy; pyv[3] = pyv[2] * dy;
        pzv[0] = 1.0f; pzv[1] = dz; pzv[2] = dz * dz; pzv[3] = pzv[2] * dz;

        const float4* __restrict__ row4 =
            reinterpret_cast<const float4*>(&s_sl[p * SLPAD]);

        float sum = 0.0f;
        #pragma unroll
        for (int k4 = 0; k4 < 16; ++k4) {     // k4 = a*4 + b (z,y)
            const float wzy = pzv[k4 >> 2] * pyv[k4 & 3];
            const float4 f = row4[k4];
            float sc = f.x;
            sc = fmaf(f.y, pxv[1], sc);
            sc = fmaf(f.z, pxv[2], sc);
            sc = fmaf(f.w, pxv[3], sc);
            sum = fmaf(sc, wzy, sum);
        }
        g_patch[(size_t)ge * PPAD + p] = sum * amp;
    }
}

// ---------------------------------------------------------------------------
// Kernel 2: render (PDL secondary). Block = (band, frame, emitter-split):
// 16 emitters, 8 rows. The prefix — bg staging, classification from xyz,
// miss-emitter cp.async.bulk copies — is independent of g_patch and overlaps
// the patch kernel. cudaGridDependencySynchronize() guards only the hit-
// emitter patch reads. JAX semantics: negative scatter targets wrap (+H/+W),
// targets >= H/W dropped.
// ---------------------------------------------------------------------------
__global__ __launch_bounds__(256) void render_kernel(const float* __restrict__ xyz,
                                                     const float* __restrict__ bg,
                                                     float* __restrict__ out)
{
    const int band  = blockIdx.x;            // 0..NBAND-1
    const int frame = blockIdx.y;            // 0..B-1
    const int esp   = blockIdx.z;            // 0..ESPLIT-1
    const int bs    = band * BAND;
    const int t     = threadIdx.x;

    __shared__ float4 s_bg[BAND_F4];         // 4 KB scaled bg band
    __shared__ int    s_r0[EPB];
    __shared__ int    s_c0[EPB];
    __shared__ unsigned char s_hit[EPB];
    __shared__ int    s_list[EPB];
    __shared__ int    s_nhit;

    if (t == 0) s_nhit = 0;

    // ---- load + scale bg band ----
    {
        const float4 b4 = reinterpret_cast<const float4*>(
            bg + (size_t)frame * PIX + (size_t)bs * W)[t];
        float4 v;
        v.x = fmaf(b4.x, P_GAIN, P_BASELINE);
        v.y = fmaf(b4.y, P_GAIN, P_BASELINE);
        v.z = fmaf(b4.z, P_GAIN, P_BASELINE);
        v.w = fmaf(b4.w, P_GAIN, P_BASELINE);
        s_bg[t] = v;
    }
    __syncthreads();

    // ---- classify this split's 16 emitters (directly from xyz) ----
    if (t < EPB) {
        const int ge = frame * E + esp * EPB + t;
        const float x = xyz[ge * 3 + 0];
        const float y = xyz[ge * 3 + 1];
        const int r0 = (int)floorf(y) - HALF;
        s_r0[t] = r0;
        s_c0[t] = (int)floorf(x) - HALF;
        int hit = 0;
        #pragma unroll
        for (int lr = 0; lr < BAND; ++lr) {
            int rr = bs + lr - r0;
            if (rr >= H) rr -= H;            // wrapped negative target row
            if ((unsigned)rr < (unsigned)R) hit = 1;
        }
        s_hit[t] = (unsigned char)hit;
        if (hit) s_list[atomicAdd(&s_nhit, 1)] = t;
    }
    __syncthreads();

    // ---- miss emitters: distributed TMA bulk copies (thread t == emitter) ----
    const bool issuer = (t < EPB) && !s_hit[t];
    if (issuer) {
        asm volatile("fence.proxy.async.shared::cta;" ::: "memory");
        uint32_t src;
        asm("{ .reg .u64 tmp; cvta.to.shared.u64 tmp, %1; cvt.u32.u64 %0, tmp; }"
            : "=r"(src) : "l"(s_bg));
        float* dst = out + (size_t)(frame * E + esp * EPB + t) * PIX
                         + (size_t)bs * W;
        asm volatile(
            "cp.async.bulk.global.shared::cta.bulk_group [%0], [%1], %2;"
            :: "l"(dst), "r"(src), "r"((unsigned)BAND_BYTES) : "memory");
        asm volatile("cp.async.bulk.commit_group;" ::: "memory");
    }

    // ---- wait for patch kernel completion only where its data is needed ----
    cudaGridDependencySynchronize();

    // ---- hit emitters: per-thread float4 STG with patch add ----
    const float4 base_v = s_bg[t];
    const int pix = t * 4;
    const int lr  = pix >> 7;                // local row (W == 128), warp-uniform
    const int col = pix & (W - 1);
    const int nhit = s_nhit;

    #pragma unroll 1
    for (int kk = 0; kk < nhit; ++kk) {
        const int em = s_list[kk];
        const int ge = frame * E + esp * EPB + em;
        const int r0 = s_r0[em];
        const int c0 = s_c0[em];
        float4 v = base_v;

        int rr = bs + lr - r0;
        if (rr >= H) rr -= H;                // wrapped negative target row
        if ((unsigned)rr < (unsigned)R) {
            const float* __restrict__ pp = g_patch + (size_t)ge * PPAD + rr * R;
            float* vp = &v.x;
            #pragma unroll
            for (int j = 0; j < 4; ++j) {
                int cj = col - c0 + j;
                if (cj >= W) cj -= W;        // wrapped negative target col
                if ((unsigned)cj < (unsigned)R) vp[j] += pp[cj];
            }
        }
        reinterpret_cast<float4*>(
            out + (size_t)ge * PIX + (size_t)bs * W)[t] = v;
    }

    // ---- each issuer drains its own bulk copy before exiting ----
    if (issuer) {
        asm volatile("cp.async.bulk.wait_group 0;" ::: "memory");
    }
}

// ---------------------------------------------------------------------------
// Launch. Patch kernel normally; render as a PDL secondary so its
// g_patch-independent prefix overlaps the patch kernel.
// Inputs identified by element count:
//   xyz [B,E,3]=6144, n_photons [B,E]=2048, bg [B,H,W]=524288,
//   coeff [D,R,R,4,4,4]=346112.  Output: [B,E,H,W] f32.
// ---------------------------------------------------------------------------
extern "C" void kernel_launch(void* const* d_in, const int* in_sizes, int n_in,
                              void* d_out, int out_size)
{
    const float* xyz   = nullptr;
    const float* nph   = nullptr;
    const float* bg    = nullptr;
    const float* coeff = nullptr;
    for (int i = 0; i < n_in; ++i) {
        switch (in_sizes[i]) {
            case B * E * 3:      xyz   = (const float*)d_in[i]; break;
            case B * E:          nph   = (const float*)d_in[i]; break;
            case B * H * W:      bg    = (const float*)d_in[i]; break;
            case D * R * R * 64: coeff = (const float*)d_in[i]; break;
        }
    }
    float* out = (float*)d_out;

    dim3 pgrid(D, NSPLIT);
    patch_kernel<<<pgrid, 256>>>(xyz, nph, coeff);

    // Render as PDL secondary on the same (default) stream.
    cudaLaunchConfig_t cfg = {};
    cfg.gridDim  = dim3(NBAND, B, ESPLIT);
    cfg.blockDim = dim3(256, 1, 1);
    cfg.dynamicSmemBytes = 0;
    cfg.stream = 0;
    cudaLaunchAttribute attrs[1];
    attrs[0].id = cudaLaunchAttributeProgrammaticStreamSerialization;
    attrs[0].val.programmaticStreamSerializationAllowed = 1;
    cfg.attrs = attrs;
    cfg.numAttrs = 1;
    cudaLaunchKernelEx(&cfg, render_kernel, xyz, bg, out);
}

// round 10
// speedup vs baseline: 1.0913x; 1.0913x over previous
#include <cuda_runtime.h>
#include <cstdint>

#define P_GAIN     2.0f
#define P_BASELINE 100.0f
static constexpr int B = 32;
static constexpr int E = 64;
static constexpr int H = 128;
static constexpr int W = 128;
static constexpr int R = 13;
static constexpr int D = 32;
static constexpr int HALF = R / 2;
static constexpr int PIX = H * W;               // 16384
static constexpr int NPX = R * R;               // 169 patch pixels
static constexpr int PPAD = 176;                // padded patch stride
static constexpr int SLPAD = 68;                // slice row pad (16B aligned, LDS.128 conflict-free)
static constexpr int BAND = 8;                  // rows per band
static constexpr int NBAND = H / BAND;          // 16
static constexpr int BAND_F4 = BAND * W / 4;    // 256 float4 per band
static constexpr int BAND_BYTES = BAND * W * 4; // 4096
static constexpr int NSPLIT = 8;                // emitter splits per z-slice
static constexpr int ESPLIT = 4;                // emitter splits in render
static constexpr int EPB = E / ESPLIT;          // 16 emitters per render block

// Scratch (static device global — no allocation)
__device__ float g_patch[B * E * PPAD];         // 1.44 MB pre-scaled patches

// ---------------------------------------------------------------------------
// Kernel 1: z-grouped patch precompute with REGISTER REUSE across emitters.
// Block = (z, split). Stage the 43KB slice [169][64] into smem once; build
// the emitter list for this (z,split). Then thread t (= patch pixel) loads
// its 64-coeff row into registers ONCE (16 LDS.128) and loops over the n
// listed emitters, so smem crossbar traffic is 43KB/block instead of
// n*43KB (~8x less) — this was the binder measured at ~15us in R8/R9.
// ---------------------------------------------------------------------------
__global__ __launch_bounds__(256) void patch_kernel(const float* __restrict__ xyz,
                                                    const float* __restrict__ nph,
                                                    const float* __restrict__ coeff)
{
    const int z     = blockIdx.x;    // 0..D-1
    const int split = blockIdx.y;    // 0..NSPLIT-1
    const int t     = threadIdx.x;

    __shared__ float s_sl[NPX * SLPAD];  // 45.97 KB padded slice
    __shared__ int   s_list[256];
    __shared__ int   s_n;

    if (t == 0) s_n = 0;

    // ---- stage slice (coalesced float4 in, aligned STS.128 out) ----
    const float4* __restrict__ c4 =
        reinterpret_cast<const float4*>(coeff + (size_t)z * NPX * 64);
    #pragma unroll 4
    for (int i4 = t; i4 < NPX * 16; i4 += 256) {   // 2704 float4
        const float4 f = c4[i4];
        const int pix = i4 >> 4;
        const int k4  = i4 & 15;
        reinterpret_cast<float4*>(&s_sl[pix * SLPAD])[k4] = f;
    }

    // ---- build emitter list for this (z, split) ----
    for (int e = t; e < B * E; e += 256) {
        if ((e & (NSPLIT - 1)) != split) continue;
        const float zv = xyz[e * 3 + 2];
        float zc = fminf(fmaxf(zv, 0.0f), (float)(D - 1) - 1e-6f);
        if ((int)floorf(zc) == z) s_list[atomicAdd(&s_n, 1)] = e;
    }
    __syncthreads();

    // ---- register-resident row, loop emitters ----
    if (t < NPX) {
        float4 c[16];
        const float4* __restrict__ row4 =
            reinterpret_cast<const float4*>(&s_sl[t * SLPAD]);
        #pragma unroll
        for (int k4 = 0; k4 < 16; ++k4) c[k4] = row4[k4];

        const int n = s_n;
        #pragma unroll 1
        for (int i = 0; i < n; ++i) {
            const int ge = s_list[i];
            const float x  = xyz[ge * 3 + 0];   // broadcast loads (L1-hot)
            const float y  = xyz[ge * 3 + 1];
            const float zv = xyz[ge * 3 + 2];
            const float dx = x - floorf(x);
            const float dy = y - floorf(y);
            float zc = fminf(fmaxf(zv, 0.0f), (float)(D - 1) - 1e-6f);
            const float dz = zc - floorf(zc);
            const float amp = nph[ge] * P_GAIN;

            const float px1 = dx, px2 = dx * dx, px3 = px2 * dx;
            float pyv[4], pzv[4];
            pyv[0] = 1.0f; pyv[1] = dy; pyv[2] = dy * dy; pyv[3] = pyv[2] * dy;
            pzv[0] = 1.0f; pzv[1] = dz; pzv[2] = dz * dz; pzv[3] = pzv[2] * dz;

            float sum = 0.0f;
            #pragma unroll
            for (int k4 = 0; k4 < 16; ++k4) {   // k4 = a*4 + b  (z,y)
                const float wzy = pzv[k4 >> 2] * pyv[k4 & 3];
                const float4 f = c[k4];
                float sc = f.x;
                sc = fmaf(f.y, px1, sc);
                sc = fmaf(f.z, px2, sc);
                sc = fmaf(f.w, px3, sc);
                sum = fmaf(sc, wzy, sum);
            }
            g_patch[(size_t)ge * PPAD + t] = sum * amp;
        }
    }
}

// ---------------------------------------------------------------------------
// Kernel 2: render (proven R8 form). Block = (band, frame, emitter-split):
// 16 emitters, 8 rows. Classification directly from xyz. Miss emitters ->
// cp.async.bulk 4KB smem->gmem issued by thread t==em (distributed). Hit
// emitters -> per-thread float4 STG with patch add from g_patch.
// JAX semantics: negative scatter targets wrap (+H/+W), >= H/W dropped.
// ---------------------------------------------------------------------------
__global__ __launch_bounds__(256) void render_kernel(const float* __restrict__ xyz,
                                                     const float* __restrict__ bg,
                                                     float* __restrict__ out)
{
    const int band  = blockIdx.x;            // 0..NBAND-1
    const int frame = blockIdx.y;            // 0..B-1
    const int esp   = blockIdx.z;            // 0..ESPLIT-1
    const int bs    = band * BAND;
    const int t     = threadIdx.x;

    __shared__ float4 s_bg[BAND_F4];         // 4 KB scaled bg band
    __shared__ int    s_r0[EPB];
    __shared__ int    s_c0[EPB];
    __shared__ unsigned char s_hit[EPB];
    __shared__ int    s_list[EPB];
    __shared__ int    s_nhit;

    if (t == 0) s_nhit = 0;

    // ---- load + scale bg band ----
    {
        const float4 b4 = reinterpret_cast<const float4*>(
            bg + (size_t)frame * PIX + (size_t)bs * W)[t];
        float4 v;
        v.x = fmaf(b4.x, P_GAIN, P_BASELINE);
        v.y = fmaf(b4.y, P_GAIN, P_BASELINE);
        v.z = fmaf(b4.z, P_GAIN, P_BASELINE);
        v.w = fmaf(b4.w, P_GAIN, P_BASELINE);
        s_bg[t] = v;
    }
    __syncthreads();

    // ---- classify this split's 16 emitters (directly from xyz) ----
    if (t < EPB) {
        const int ge = frame * E + esp * EPB + t;
        const float x = xyz[ge * 3 + 0];
        const float y = xyz[ge * 3 + 1];
        const int r0 = (int)floorf(y) - HALF;
        s_r0[t] = r0;
        s_c0[t] = (int)floorf(x) - HALF;
        int hit = 0;
        #pragma unroll
        for (int lr = 0; lr < BAND; ++lr) {
            int rr = bs + lr - r0;
            if (rr >= H) rr -= H;            // wrapped negative target row
            if ((unsigned)rr < (unsigned)R) hit = 1;
        }
        s_hit[t] = (unsigned char)hit;
        if (hit) s_list[atomicAdd(&s_nhit, 1)] = t;
    }
    __syncthreads();

    // ---- miss emitters: distributed TMA bulk copies (thread t == emitter) ----
    const bool issuer = (t < EPB) && !s_hit[t];
    if (issuer) {
        asm volatile("fence.proxy.async.shared::cta;" ::: "memory");
        uint32_t src;
        asm("{ .reg .u64 tmp; cvta.to.shared.u64 tmp, %1; cvt.u32.u64 %0, tmp; }"
            : "=r"(src) : "l"(s_bg));
        float* dst = out + (size_t)(frame * E + esp * EPB + t) * PIX
                         + (size_t)bs * W;
        asm volatile(
            "cp.async.bulk.global.shared::cta.bulk_group [%0], [%1], %2;"
            :: "l"(dst), "r"(src), "r"((unsigned)BAND_BYTES) : "memory");
        asm volatile("cp.async.bulk.commit_group;" ::: "memory");
    }

    // ---- hit emitters: per-thread float4 STG with patch add ----
    const float4 base_v = s_bg[t];
    const int pix = t * 4;
    const int lr  = pix >> 7;                // local row (W == 128), warp-uniform
    const int col = pix & (W - 1);
    const int nhit = s_nhit;

    #pragma unroll 1
    for (int kk = 0; kk < nhit; ++kk) {
        const int em = s_list[kk];
        const int ge = frame * E + esp * EPB + em;
        const int r0 = s_r0[em];
        const int c0 = s_c0[em];
        float4 v = base_v;

        int rr = bs + lr - r0;
        if (rr >= H) rr -= H;                // wrapped negative target row
        if ((unsigned)rr < (unsigned)R) {
            const float* __restrict__ pp = g_patch + (size_t)ge * PPAD + rr * R;
            float* vp = &v.x;
            #pragma unroll
            for (int j = 0; j < 4; ++j) {
                int cj = col - c0 + j;
                if (cj >= W) cj -= W;        // wrapped negative target col
                if ((unsigned)cj < (unsigned)R) vp[j] += pp[cj];
            }
        }
        reinterpret_cast<float4*>(
            out + (size_t)ge * PIX + (size_t)bs * W)[t] = v;
    }

    // ---- each issuer drains its own bulk copy before exiting ----
    if (issuer) {
        asm volatile("cp.async.bulk.wait_group 0;" ::: "memory");
    }
}

// ---------------------------------------------------------------------------
// Launch. Inputs identified by element count:
//   xyz [B,E,3]=6144, n_photons [B,E]=2048, bg [B,H,W]=524288,
//   coeff [D,R,R,4,4,4]=346112.  Output: [B,E,H,W] f32.
// ---------------------------------------------------------------------------
extern "C" void kernel_launch(void* const* d_in, const int* in_sizes, int n_in,
                              void* d_out, int out_size)
{
    const float* xyz   = nullptr;
    const float* nph   = nullptr;
    const float* bg    = nullptr;
    const float* coeff = nullptr;
    for (int i = 0; i < n_in; ++i) {
        switch (in_sizes[i]) {
            case B * E * 3:      xyz   = (const float*)d_in[i]; break;
            case B * E:          nph   = (const float*)d_in[i]; break;
            case B * H * W:      bg    = (const float*)d_in[i]; break;
            case D * R * R * 64: coeff = (const float*)d_in[i]; break;
        }
    }
    float* out = (float*)d_out;

    dim3 pgrid(D, NSPLIT);
    patch_kernel<<<pgrid, 256>>>(xyz, nph, coeff);

    dim3 rgrid(NBAND, B, ESPLIT);
    render_kernel<<<rgrid, 256>>>(xyz, bg, out);
}

// round 11
// speedup vs baseline: 1.2892x; 1.1813x over previous
#include <cuda_runtime.h>
#include <cstdint>

#define P_GAIN     2.0f
#define P_BASELINE 100.0f
static constexpr int B = 32;
static constexpr int E = 64;
static constexpr int H = 128;
static constexpr int W = 128;
static constexpr int R = 13;
static constexpr int D = 32;
static constexpr int HALF = R / 2;
static constexpr int PIX = H * W;               // 16384
static constexpr int NPX = R * R;               // 169 patch pixels
static constexpr int PPAD = 176;                // padded patch stride
static constexpr int SLPAD = 68;                // slice row pad
static constexpr int BAND = 8;                  // rows per band
static constexpr int NBAND = H / BAND;          // 16
static constexpr int BAND_F4 = BAND * W / 4;    // 256 float4 per band
static constexpr int BAND_BYTES = BAND * W * 4; // 4096
static constexpr int NSPLIT = 8;                // emitter splits per z-slice
static constexpr int ESPLIT = 4;                // emitter splits in render
static constexpr int EPB = E / ESPLIT;          // 16 emitters per render block
static constexpr int NSTAGE = 4;                // hit staging buffers

// Scratch (static device global — no allocation)
__device__ float g_patch[B * E * PPAD];         // 1.44 MB pre-scaled patches

__device__ __forceinline__ uint64_t evict_first_policy() {
    uint64_t pol;
    asm("createpolicy.fractional.L2::evict_first.b64 %0, 1.0;" : "=l"(pol));
    return pol;
}

__device__ __forceinline__ uint32_t smem_u32(const void* p) {
    uint32_t a;
    asm("{ .reg .u64 tmp; cvta.to.shared.u64 tmp, %1; cvt.u32.u64 %0, tmp; }"
        : "=r"(a) : "l"(p));
    return a;
}

__device__ __forceinline__ void bulk_store(float* dst, uint32_t src,
                                           unsigned bytes, uint64_t pol) {
    asm volatile(
        "cp.async.bulk.global.shared::cta.bulk_group.L2::cache_hint "
        "[%0], [%1], %2, %3;"
        :: "l"(dst), "r"(src), "r"(bytes), "l"(pol) : "memory");
}

// ---------------------------------------------------------------------------
// Kernel 1: z-grouped patch precompute (R10 form — runs under the previous
// iteration's write drain, so its own cost is mostly hidden).
// ---------------------------------------------------------------------------
__global__ __launch_bounds__(256) void patch_kernel(const float* __restrict__ xyz,
                                                    const float* __restrict__ nph,
                                                    const float* __restrict__ coeff)
{
    const int z     = blockIdx.x;
    const int split = blockIdx.y;
    const int t     = threadIdx.x;

    __shared__ float s_sl[NPX * SLPAD];
    __shared__ int   s_list[256];
    __shared__ int   s_n;

    if (t == 0) s_n = 0;

    const float4* __restrict__ c4 =
        reinterpret_cast<const float4*>(coeff + (size_t)z * NPX * 64);
    #pragma unroll 4
    for (int i4 = t; i4 < NPX * 16; i4 += 256) {
        const float4 f = c4[i4];
        reinterpret_cast<float4*>(&s_sl[(i4 >> 4) * SLPAD])[i4 & 15] = f;
    }

    for (int e = t; e < B * E; e += 256) {
        if ((e & (NSPLIT - 1)) != split) continue;
        const float zv = xyz[e * 3 + 2];
        float zc = fminf(fmaxf(zv, 0.0f), (float)(D - 1) - 1e-6f);
        if ((int)floorf(zc) == z) s_list[atomicAdd(&s_n, 1)] = e;
    }
    __syncthreads();

    if (t < NPX) {
        float4 c[16];
        const float4* __restrict__ row4 =
            reinterpret_cast<const float4*>(&s_sl[t * SLPAD]);
        #pragma unroll
        for (int k4 = 0; k4 < 16; ++k4) c[k4] = row4[k4];

        const int n = s_n;
        #pragma unroll 1
        for (int i = 0; i < n; ++i) {
            const int ge = s_list[i];
            const float x  = xyz[ge * 3 + 0];
            const float y  = xyz[ge * 3 + 1];
            const float zv = xyz[ge * 3 + 2];
            const float dx = x - floorf(x);
            const float dy = y - floorf(y);
            float zc = fminf(fmaxf(zv, 0.0f), (float)(D - 1) - 1e-6f);
            const float dz = zc - floorf(zc);
            const float amp = nph[ge] * P_GAIN;

            const float px1 = dx, px2 = dx * dx, px3 = px2 * dx;
            float pyv[4], pzv[4];
            pyv[0] = 1.0f; pyv[1] = dy; pyv[2] = dy * dy; pyv[3] = pyv[2] * dy;
            pzv[0] = 1.0f; pzv[1] = dz; pzv[2] = dz * dz; pzv[3] = pzv[2] * dz;

            float sum = 0.0f;
            #pragma unroll
            for (int k4 = 0; k4 < 16; ++k4) {
                const float wzy = pzv[k4 >> 2] * pyv[k4 & 3];
                const float4 f = c[k4];
                float sc = f.x;
                sc = fmaf(f.y, px1, sc);
                sc = fmaf(f.z, px2, sc);
                sc = fmaf(f.w, px3, sc);
                sum = fmaf(sc, wzy, sum);
            }
            g_patch[(size_t)ge * PPAD + t] = sum * amp;
        }
    }
}

// ---------------------------------------------------------------------------
// Kernel 2: render — ALL output leaves via TMA bulk stores with
// L2::evict_first (no per-thread STG to the output at all).
//   miss emitters: bulk store straight from s_bg (distributed issuers)
//   hit  emitters: compose band (+patch) in a rotating smem stage (STS only),
//                  then one bulk store per hit.
// JAX semantics: negative scatter targets wrap (+H/+W), >= H/W dropped.
// ---------------------------------------------------------------------------
__global__ __launch_bounds__(256) void render_kernel(const float* __restrict__ xyz,
                                                     const float* __restrict__ bg,
                                                     float* __restrict__ out)
{
    const int band  = blockIdx.x;            // 0..NBAND-1
    const int frame = blockIdx.y;            // 0..B-1
    const int esp   = blockIdx.z;            // 0..ESPLIT-1
    const int bs    = band * BAND;
    const int t     = threadIdx.x;

    __shared__ float4 s_bg[BAND_F4];                 // 4 KB scaled bg band
    __shared__ float4 s_st[NSTAGE][BAND_F4];         // 16 KB hit staging
    __shared__ int    s_r0[EPB];
    __shared__ int    s_c0[EPB];
    __shared__ unsigned char s_hit[EPB];
    __shared__ int    s_list[EPB];
    __shared__ int    s_nhit;

    if (t == 0) s_nhit = 0;

    const uint64_t pol = evict_first_policy();
    const size_t out_base = ((size_t)frame * E + esp * EPB) * PIX + (size_t)bs * W;

    // ---- load + scale bg band ----
    {
        const float4 b4 = reinterpret_cast<const float4*>(
            bg + (size_t)frame * PIX + (size_t)bs * W)[t];
        float4 v;
        v.x = fmaf(b4.x, P_GAIN, P_BASELINE);
        v.y = fmaf(b4.y, P_GAIN, P_BASELINE);
        v.z = fmaf(b4.z, P_GAIN, P_BASELINE);
        v.w = fmaf(b4.w, P_GAIN, P_BASELINE);
        s_bg[t] = v;
    }
    __syncthreads();

    // ---- classify this split's 16 emitters ----
    if (t < EPB) {
        const int ge = frame * E + esp * EPB + t;
        const float x = xyz[ge * 3 + 0];
        const float y = xyz[ge * 3 + 1];
        const int r0 = (int)floorf(y) - HALF;
        s_r0[t] = r0;
        s_c0[t] = (int)floorf(x) - HALF;
        int hit = 0;
        #pragma unroll
        for (int lr = 0; lr < BAND; ++lr) {
            int rr = bs + lr - r0;
            if (rr >= H) rr -= H;            // wrapped negative target row
            if ((unsigned)rr < (unsigned)R) hit = 1;
        }
        s_hit[t] = (unsigned char)hit;
        if (hit) s_list[atomicAdd(&s_nhit, 1)] = t;
    }
    __syncthreads();

    // ---- miss emitters: distributed bulk stores from s_bg ----
    const bool issuer = (t < EPB) && !s_hit[t];
    if (issuer) {
        asm volatile("fence.proxy.async.shared::cta;" ::: "memory");
        bulk_store(out + out_base + (size_t)t * PIX, smem_u32(s_bg),
                   (unsigned)BAND_BYTES, pol);
        asm volatile("cp.async.bulk.commit_group;" ::: "memory");
    }

    // ---- hit emitters: compose in staging smem, bulk store ----
    const float4 base_v = s_bg[t];
    const int pix = t * 4;
    const int lr  = pix >> 7;                // local row (W == 128), warp-uniform
    const int col = pix & (W - 1);
    const int nhit = s_nhit;

    #pragma unroll 1
    for (int kk = 0; kk < nhit; ++kk) {
        const int em = s_list[kk];
        const int ge = frame * E + esp * EPB + em;
        const int r0 = s_r0[em];
        const int c0 = s_c0[em];
        const int sb = kk & (NSTAGE - 1);

        // rare: buffer reuse — drain our own pending bulk reads first
        if (kk >= NSTAGE) {
            if (t == 0)
                asm volatile("cp.async.bulk.wait_group.read 0;" ::: "memory");
            __syncthreads();
        }

        float4 v = base_v;
        int rr = bs + lr - r0;
        if (rr >= H) rr -= H;                // wrapped negative target row
        if ((unsigned)rr < (unsigned)R) {
            const float* __restrict__ pp = g_patch + (size_t)ge * PPAD + rr * R;
            float* vp = &v.x;
            #pragma unroll
            for (int j = 0; j < 4; ++j) {
                int cj = col - c0 + j;
                if (cj >= W) cj -= W;        // wrapped negative target col
                if ((unsigned)cj < (unsigned)R) vp[j] += pp[cj];
            }
        }
        s_st[sb][t] = v;
        __syncthreads();

        if (t == 0) {
            asm volatile("fence.proxy.async.shared::cta;" ::: "memory");
            bulk_store(out + out_base + (size_t)em * PIX, smem_u32(s_st[sb]),
                       (unsigned)BAND_BYTES, pol);
            asm volatile("cp.async.bulk.commit_group;" ::: "memory");
        }
    }

    // ---- drain: every thread with pending groups waits for reads ----
    if (issuer || t == 0) {
        asm volatile("cp.async.bulk.wait_group.read 0;" ::: "memory");
    }
    __syncthreads();   // smem lifetime: no thread exits while TMA may read
}

// ---------------------------------------------------------------------------
// Launch. Inputs identified by element count:
//   xyz [B,E,3]=6144, n_photons [B,E]=2048, bg [B,H,W]=524288,
//   coeff [D,R,R,4,4,4]=346112.  Output: [B,E,H,W] f32.
// ---------------------------------------------------------------------------
extern "C" void kernel_launch(void* const* d_in, const int* in_sizes, int n_in,
                              void* d_out, int out_size)
{
    const float* xyz   = nullptr;
    const float* nph   = nullptr;
    const float* bg    = nullptr;
    const float* coeff = nullptr;
    for (int i = 0; i < n_in; ++i) {
        switch (in_sizes[i]) {
            case B * E * 3:      xyz   = (const float*)d_in[i]; break;
            case B * E:          nph   = (const float*)d_in[i]; break;
            case B * H * W:      bg    = (const float*)d_in[i]; break;
            case D * R * R * 64: coeff = (const float*)d_in[i]; break;
        }
    }
    float* out = (float*)d_out;

    dim3 pgrid(D, NSPLIT);
    patch_kernel<<<pgrid, 256>>>(xyz, nph, coeff);

    dim3 rgrid(NBAND, B, ESPLIT);
    render_kernel<<<rgrid, 256>>>(xyz, bg, out);
}